// round 13
// baseline (speedup 1.0000x reference)
#include <cuda_runtime.h>
#include <cuda_fp16.h>
#include <cstdint>

#define Bsz 16
#define Cin 128
#define Hh 64
#define Ww 64
#define HW 4096
#define Oc 256
#define ROWLEN 1152
#define ADIM 1161
#define TBL 1024
#define Rr 2.5f
#define Uu 0.83f
#define CONV_ELEMS 16777216LL

// ---------------------------------------------------------------------------
__device__ int g_count[TBL];
__device__ int g_done;
__device__ int g_maskA[Oc];
__device__ int g_active[Oc];
__device__ int g_nactive;
__device__ float g_dotv[Oc];
__device__ float g_nrm[Oc];
__device__ float g_T[Bsz * 9 * HW];
__device__ __half g_Ah[9 * 256 * 128];             // weights [k][m][perm(c)] fp16
__device__ __half g_Bh[(size_t)Bsz * HW * Cin];    // input NHWC fp16, perm(c)

// ---------------------------------------------------------------------------
__device__ __forceinline__ void cp_async16(uint32_t dst, const void* src, bool valid) {
    int sz = valid ? 16 : 0;
    asm volatile("cp.async.cg.shared.global [%0], [%1], 16, %2;" :: "r"(dst), "l"(src), "r"(sz) : "memory");
}
#define CP_COMMIT() asm volatile("cp.async.commit_group;" ::: "memory")
#define CP_WAIT(n) asm volatile("cp.async.wait_group %0;" :: "n"(n) : "memory")

__device__ __forceinline__ uint32_t smem_u32(const void* p) {
    uint32_t a;
    asm("{ .reg .u64 t; cvta.to.shared.u64 t, %1; cvt.u32.u64 %0, t; }" : "=r"(a) : "l"(p));
    return a;
}

#define MMA16816F(d, a, b0_, b1_) \
    asm volatile("mma.sync.aligned.m16n8k16.row.col.f32.f16.f16.f32 " \
        "{%0,%1,%2,%3}, {%4,%5,%6,%7}, {%8,%9}, {%0,%1,%2,%3};" \
        : "+f"((d)[0]), "+f"((d)[1]), "+f"((d)[2]), "+f"((d)[3]) \
        : "r"((a)[0]), "r"((a)[1]), "r"((a)[2]), "r"((a)[3]), "r"(b0_), "r"(b1_))

// ---------------------------------------------------------------------------
// votePrepHash: grid 288.
//  blocks [0,256): per 256-px tile -- read input once, emit vote partials
//    (g_T) AND fp16 NHWC (g_Bh, channel-pair-permuted) via smem transpose.
//  blocks [256,288): kernel-row hash partials; zero g_count / g_done.
// ---------------------------------------------------------------------------
#define VP_PITCH 257
#define VP_SMEM 71936

__global__ void votePrepHash_kernel(const float* __restrict__ in,
                                    const float* __restrict__ kern,
                                    const float* __restrict__ a) {
    extern __shared__ char vsm[];
    int tid = threadIdx.x;
    int bx = blockIdx.x;

    if (bx >= 256) {
        int hb = bx - 256;
        if (tid < 32) g_count[hb * 32 + tid] = 0;
        if (hb == 0 && tid == 32) g_done = 0;
        int wid = tid >> 5, lane = tid & 31;
        int row = hb * 8 + wid;
        const float4* kr = reinterpret_cast<const float4*>(kern + (size_t)row * ROWLEN);
        const float4* a4 = reinterpret_cast<const float4*>(a);
        float s = 0.f, d = 0.f;
        for (int j = lane; j < ROWLEN / 4; j += 32) {
            float4 kv = kr[j], av = __ldg(&a4[j]);
            s += kv.x * kv.x + kv.y * kv.y + kv.z * kv.z + kv.w * kv.w;
            d += kv.x * av.x + kv.y * av.y + kv.z * av.z + kv.w * av.w;
        }
#pragma unroll
        for (int o = 16; o > 0; o >>= 1) {
            s += __shfl_xor_sync(0xffffffff, s, o);
            d += __shfl_xor_sync(0xffffffff, d, o);
        }
        if (lane == 0) { g_dotv[row] = d; g_nrm[row] = s; }
        return;
    }

    float* w_s = (float*)vsm;
    __half* tile = (__half*)(vsm + 6144);

    for (int i = tid; i < ROWLEN; i += 256) {
        int c = i / 9, k = i % 9;
        w_s[c * 12 + k] = a[i];
    }
    __syncthreads();

    int g = bx << 8;
    int b = g >> 12;
    int px0 = g & 4095;
    const float* ip = in + (size_t)b * Cin * HW + px0 + tid;

    float acc[9];
#pragma unroll
    for (int k = 0; k < 9; k++) acc[k] = 0.f;

#pragma unroll 4
    for (int c = 0; c < Cin; c++) {
        float v = ip[(size_t)c * HW];
        tile[c * VP_PITCH + tid] = __float2half_rn(v);
        float4 w0 = *reinterpret_cast<const float4*>(&w_s[c * 12]);
        float4 w1 = *reinterpret_cast<const float4*>(&w_s[c * 12 + 4]);
        float w8 = w_s[c * 12 + 8];
        acc[0] += v * w0.x; acc[1] += v * w0.y; acc[2] += v * w0.z; acc[3] += v * w0.w;
        acc[4] += v * w1.x; acc[5] += v * w1.y; acc[6] += v * w1.z; acc[7] += v * w1.w;
        acc[8] += v * w8;
    }
    float* tp = g_T + (size_t)b * 9 * HW + px0 + tid;
#pragma unroll
    for (int k = 0; k < 9; k++) tp[k * HW] = acc[k];
    __syncthreads();

    // NHWC writes, channel-pair permuted: slot s within a 16-channel group
    // holds channels (2q, 2q+1) for s=2q (even) and (2q+8, 2q+9) for s=2q+1.
    for (int i = tid; i < 256 * 64; i += 256) {
        int p = i >> 6, slot = i & 63;
        int g16 = slot >> 3, s = slot & 7;
        int c0 = g16 * 16 + ((s & 1) ? ((s >> 1) << 1) + 8 : ((s >> 1) << 1));
        __half h0 = tile[c0 * VP_PITCH + p];
        __half h1 = tile[(c0 + 1) * VP_PITCH + p];
        reinterpret_cast<__half2*>(g_Bh)[(((size_t)(g + p)) << 6) + slot] =
            __halves2half2(h0, h1);
    }
}

// ---------------------------------------------------------------------------
// voteBCombine: 256 blocks x 256 px; last block runs combine.
// ---------------------------------------------------------------------------
__global__ void voteBCombine_kernel(const float* __restrict__ a,
                                    const float* __restrict__ bptr,
                                    float* __restrict__ out, long long out_size) {
    __shared__ int hist[TBL];
    __shared__ float ae[9];
    __shared__ int slast;
    int tid = threadIdx.x;
    for (int i = tid; i < TBL; i += 256) hist[i] = 0;
    if (tid < 9) ae[tid] = a[ROWLEN + tid];
    __syncthreads();

    int g = (blockIdx.x << 8) + tid;
    int b = g >> 12;
    int p = g & 4095;
    int y = p >> 6, x = p & 63;
    const float* tb = g_T + (size_t)b * 9 * HW;
    float s = 0.f;
#pragma unroll
    for (int dy = 0; dy < 3; dy++) {
        int gy = y + dy - 1;
        if (gy < 0 || gy >= Hh) continue;
#pragma unroll
        for (int dx = 0; dx < 3; dx++) {
            int gx = x + dx - 1;
            if (gx < 0 || gx >= Ww) continue;
            int k = dy * 3 + dx;
            s += tb[k * HW + gy * Ww + gx] + 0.5f * ae[k];
        }
    }
    int vi = (int)floorf((s + bptr[0]) / Rr);
    int vb = vi % TBL;
    if (vb < 0) vb = -vb;
    atomicAdd(&hist[vb], 1);
    __syncthreads();
    for (int i = tid; i < TBL; i += 256) {
        int c = hist[i];
        if (c) atomicAdd(&g_count[i], c);
    }

    __threadfence();
    __syncthreads();
    if (tid == 0) slast = (atomicAdd(&g_done, 1) == (int)gridDim.x - 1) ? 1 : 0;
    __syncthreads();
    if (!slast) return;

    __shared__ float sred[256];
    __shared__ int sbkt[Oc];
    __shared__ int sval[256];
    __shared__ int sidx[256];
    __shared__ int snact;
    if (tid == 0) snact = 0;
    sred[tid] = g_nrm[tid];
    __syncthreads();
    for (int st = 128; st > 0; st >>= 1) {
        if (tid < st) sred[tid] = fmaxf(sred[tid], sred[tid + st]);
        __syncthreads();
    }
    {
        float sn = g_nrm[tid];
        float scale = Uu / sqrtf(sred[0]);
        float dot = scale * g_dotv[tid];
        float pw = scale * scale * sn;
        float acc = 0.f, tt = pw;
#pragma unroll
        for (int i = 0; i < 9; i++) { acc += tt * ae[i]; tt = tt * tt; }
        int hi = (int)floorf((dot + acc + bptr[0]) / Rr);
        int bkt = hi % TBL;
        if (bkt < 0) bkt = -bkt;
        sbkt[tid] = bkt;
    }
    int bv = -1, bi = 0;
#pragma unroll
    for (int q = 0; q < 4; q++) {
        int idx = tid + q * 256;
        int v = *((volatile int*)&g_count[idx]);
        if (v > bv) { bv = v; bi = idx; }
    }
    sval[tid] = bv;
    sidx[tid] = bi;
    __syncthreads();
    for (int st = 128; st > 0; st >>= 1) {
        if (tid < st) {
            int v2 = sval[tid + st], i2 = sidx[tid + st];
            if (v2 > sval[tid] || (v2 == sval[tid] && i2 < sidx[tid])) {
                sval[tid] = v2;
                sidx[tid] = i2;
            }
        }
        __syncthreads();
    }
    int winner = sidx[0];
    {
        int m = (sbkt[tid] == winner) ? 1 : 0;
        g_maskA[tid] = m;
        if (m) { int pos = atomicAdd(&snact, 1); g_active[pos] = tid; }
        if (out_size >= CONV_ELEMS + 1 + Oc) out[CONV_ELEMS + 1 + tid] = m ? 1.f : 0.f;
    }
    if (tid == 0 && out_size >= CONV_ELEMS + 1) out[CONV_ELEMS] = (float)winner;
    __syncthreads();
    if (tid == 0) g_nactive = snact;
}

// ---------------------------------------------------------------------------
// prepA: gather compacted active weights -> g_Ah fp16, channel-pair permuted.
// idx is the DESTINATION index; source channel derived from permuted pos.
// ---------------------------------------------------------------------------
__global__ void prepA_kernel(const float* __restrict__ kern) {
    int idx = blockIdx.x * 256 + threadIdx.x;
    int pos = idx & 127;
    int m = (idx >> 7) & 255;
    int k = idx >> 15;
    // invert permutation: within 16-group, pos = 4q + 2*hi + j  ->  c = 2q + 8*hi + j
    int q = (pos & 15) >> 2;
    int r = pos & 3;
    int c = (pos & ~15) | (2 * q + 8 * ((r >> 1) & 1) + (r & 1));
    int nact = g_nactive;
    float v = 0.f;
    if (m < nact) {
        int oc = g_active[m];
        v = kern[(size_t)oc * ROWLEN + c * 9 + k];
    }
    g_Ah[idx] = __float2half_rn(v);
}

// ---------------------------------------------------------------------------
// Main conv: 9 shifted GEMMs, single-term fp16, compacted oc list,
// permuted-pair LDS.64 fragments.
// grid (512, 5): by<4 conv tiles (M=128px x N=64oc, exit if n0>=nact);
// by==4 zeroes inactive output planes.
// 8 warps 4(M)x2(N); 9 full-K double-buffered steps.
// smem: patch 264px x 288B [0,76032), weights 2 x 64 x 288B [76032,112896),
//       act [112896,113152)
// ---------------------------------------------------------------------------
#define PSTR 144                       // halfs per pixel row (288 B)
#define PROWB (PSTR * 2)
#define SM_PH 0
#define SM_W 76032
#define WBUF 18432
#define WROWB 288
#define SM_ACT 112896
#define SM_TOT 113152

__global__ void __launch_bounds__(256, 2)
conv_mma_kernel(float* __restrict__ out) {
    extern __shared__ char smem[];
    const int tid = threadIdx.x;
    const int lane = tid & 31;
    const int wid = tid >> 5;
    const int nact = g_nactive;

    if (blockIdx.y == 4) {
        float4 z = make_float4(0.f, 0.f, 0.f, 0.f);
        for (int plane = blockIdx.x; plane < 4096; plane += 512) {
            if (g_maskA[plane & 255]) continue;
            float4* p = reinterpret_cast<float4*>(out + (size_t)plane * HW);
#pragma unroll
            for (int i = 0; i < 4; i++) p[tid + i * 256] = z;
        }
        return;
    }

    const int n0 = blockIdx.y << 6;
    if (n0 >= nact) return;

    const int pxg = blockIdx.x << 7;
    const int bb = pxg >> 12;
    const int y0 = (pxg & 4095) >> 6;

    uint32_t sb = smem_u32(smem);

    if (tid < 64) {
        int nn = n0 + tid;
        ((int*)(smem + SM_ACT))[tid] = (nn < nact) ? g_active[nn] : -1;
    }

    // patch: 264 px-rows x 16 chunks
    for (int i = tid; i < 264 * 16; i += 256) {
        int row = i >> 4, ch = i & 15;
        int pr = row / 66, pc = row - pr * 66;
        int gy = y0 - 1 + pr, gx = pc - 1;
        bool v = ((unsigned)gy < 64u) && ((unsigned)gx < 64u);
        const __half* src = v ? g_Bh + (((size_t)(bb << 12) + gy * 64 + gx) * 128 + ch * 8) : g_Bh;
        cp_async16(sb + SM_PH + row * PROWB + ch * 16, src, v);
    }
    // weights step 0 (k=0, full 128 c): 64 rows x 16 chunks
    for (int i = tid; i < 1024; i += 256) {
        int row = i >> 4, c16 = i & 15;
        const __half* src = g_Ah + ((size_t)(n0 + row) * 128 + c16 * 8);
        cp_async16(sb + SM_W + row * WROWB + c16 * 16, src, true);
    }
    CP_COMMIT();

    float d[2][4][4];
#pragma unroll
    for (int a = 0; a < 2; a++)
#pragma unroll
        for (int b2 = 0; b2 < 4; b2++)
#pragma unroll
            for (int c = 0; c < 4; c++) d[a][b2][c] = 0.f;

    const int pxbase = (wid & 3) << 5;   // 0,32,64,96
    const int nbase = (wid >> 2) << 5;   // 0,32
    const int rr = lane >> 2;
    const int qh = (lane & 3) << 2;      // half offset within 16-chunk

    for (int s = 0; s < 9; s++) {
        if (s < 8) {
            int k1 = s + 1;
            for (int i = tid; i < 1024; i += 256) {
                int row = i >> 4, c16 = i & 15;
                const __half* src = g_Ah + ((size_t)(k1 * 256 + n0 + row) * 128 + c16 * 8);
                cp_async16(sb + SM_W + (k1 & 1) * WBUF + row * WROWB + c16 * 16, src, true);
            }
            CP_COMMIT();
            CP_WAIT(1);
        } else {
            CP_WAIT(0);
        }
        __syncthreads();

        const int dy = s / 3, dx = s - dy * 3;
        const char* WH = smem + SM_W + (s & 1) * WBUF;

        int ebase[2];
#pragma unroll
        for (int mf = 0; mf < 2; mf++) {
            int px = pxbase + mf * 16 + rr;
            ebase[mf] = (((px >> 6) + dy) * 66 + (px & 63) + dx) * PSTR;
        }

#pragma unroll
        for (int cs = 0; cs < 8; cs++) {
            const int cl = cs * 16;
            uint32_t ah[2][4];
#pragma unroll
            for (int mf = 0; mf < 2; mf++) {
                int o = ebase[mf] + cl + qh;
                uint2 v0 = *(const uint2*)(smem + SM_PH + 2 * o);
                uint2 v1 = *(const uint2*)(smem + SM_PH + 2 * (o + 8 * PSTR));
                ah[mf][0] = v0.x; ah[mf][2] = v0.y;
                ah[mf][1] = v1.x; ah[mf][3] = v1.y;
            }
#pragma unroll
            for (int nf = 0; nf < 4; nf++) {
                int n = nbase + nf * 8 + rr;
                uint2 w = *(const uint2*)(WH + n * WROWB + (cl + qh) * 2);
#pragma unroll
                for (int mf = 0; mf < 2; mf++) {
                    MMA16816F(d[mf][nf], ah[mf], w.x, w.y);
                }
            }
        }
        __syncthreads();
    }

    // epilogue: compacted oc scatter
    const int* act = (const int*)(smem + SM_ACT);
#pragma unroll
    for (int mf = 0; mf < 2; mf++) {
#pragma unroll
        for (int nf = 0; nf < 4; nf++) {
            int col = nbase + nf * 8 + (lane & 3) * 2;
            int oc0 = act[col];
            int oc1 = act[col + 1];
#pragma unroll
            for (int h = 0; h < 2; h++) {
                int row = pxbase + mf * 16 + rr + h * 8;
                int y = y0 + (row >> 6);
                int x = row & 63;
                size_t pixoff = (size_t)y * 64 + x;
                if (oc0 >= 0) out[(((size_t)bb * Oc + oc0) << 12) + pixoff] = d[mf][nf][h * 2 + 0];
                if (oc1 >= 0) out[(((size_t)bb * Oc + oc1) << 12) + pixoff] = d[mf][nf][h * 2 + 1];
            }
        }
    }
}

// ---------------------------------------------------------------------------
extern "C" void kernel_launch(void* const* d_in, const int* in_sizes, int n_in,
                              void* d_out, int out_size) {
    const float* inp = (const float*)d_in[0];
    const float* kern = (const float*)d_in[1];
    const float* a = (const float*)d_in[2];
    const float* b = (const float*)d_in[3];
    float* out = (float*)d_out;

    cudaFuncSetAttribute(votePrepHash_kernel,
                         cudaFuncAttributeMaxDynamicSharedMemorySize, VP_SMEM);
    cudaFuncSetAttribute(conv_mma_kernel,
                         cudaFuncAttributeMaxDynamicSharedMemorySize, SM_TOT);

    votePrepHash_kernel<<<288, 256, VP_SMEM>>>(inp, kern, a);
    voteBCombine_kernel<<<256, 256>>>(a, b, out, (long long)out_size);
    prepA_kernel<<<1152, 256>>>(kern);
    conv_mma_kernel<<<dim3(512, 5), 256, SM_TOT>>>(out);
}

// round 14
// speedup vs baseline: 1.0411x; 1.0411x over previous
#include <cuda_runtime.h>
#include <cuda_fp16.h>
#include <cstdint>

#define Bsz 16
#define Cin 128
#define Hh 64
#define Ww 64
#define HW 4096
#define Oc 256
#define ROWLEN 1152
#define ADIM 1161
#define TBL 1024
#define Rr 2.5f
#define Uu 0.83f
#define CONV_ELEMS 16777216LL

// ---------------------------------------------------------------------------
__device__ int g_count[TBL];
__device__ int g_done;
__device__ int g_maskA[Oc];
__device__ int g_active[Oc];
__device__ int g_nactive;
__device__ float g_dotv[Oc];
__device__ float g_nrm[Oc];
__device__ float g_T[Bsz * 9 * HW];
__device__ __half g_Ah[9 * 256 * 128];             // weights [k][m][c] fp16 (compacted)
__device__ __half g_Bh[(size_t)Bsz * HW * Cin];    // input NHWC fp16

// ---------------------------------------------------------------------------
__device__ __forceinline__ void cp_async16(uint32_t dst, const void* src, bool valid) {
    int sz = valid ? 16 : 0;
    asm volatile("cp.async.cg.shared.global [%0], [%1], 16, %2;" :: "r"(dst), "l"(src), "r"(sz) : "memory");
}
#define CP_COMMIT() asm volatile("cp.async.commit_group;" ::: "memory")
#define CP_WAIT(n) asm volatile("cp.async.wait_group %0;" :: "n"(n) : "memory")

__device__ __forceinline__ uint32_t smem_u32(const void* p) {
    uint32_t a;
    asm("{ .reg .u64 t; cvta.to.shared.u64 t, %1; cvt.u32.u64 %0, t; }" : "=r"(a) : "l"(p));
    return a;
}

#define MMA16816F(d, a, b0_, b1_) \
    asm volatile("mma.sync.aligned.m16n8k16.row.col.f32.f16.f16.f32 " \
        "{%0,%1,%2,%3}, {%4,%5,%6,%7}, {%8,%9}, {%0,%1,%2,%3};" \
        : "+f"((d)[0]), "+f"((d)[1]), "+f"((d)[2]), "+f"((d)[3]) \
        : "r"((a)[0]), "r"((a)[1]), "r"((a)[2]), "r"((a)[3]), "r"(b0_), "r"(b1_))

#define LDSM_X4(r0, r1, r2, r3, addr) \
    asm volatile("ldmatrix.sync.aligned.m8n8.x4.shared.b16 {%0,%1,%2,%3}, [%4];" \
        : "=r"(r0), "=r"(r1), "=r"(r2), "=r"(r3) : "r"(addr))

// ---------------------------------------------------------------------------
// votePrepHash: grid 288.
//  blocks [0,256): per 256-px tile -- read input once, emit vote partials
//    (g_T) AND fp16 NHWC (g_Bh) via smem transpose.
//  blocks [256,288): kernel-row hash partials; zero g_count / g_done.
// ---------------------------------------------------------------------------
#define VP_PITCH 257
#define VP_SMEM 71936

__global__ void votePrepHash_kernel(const float* __restrict__ in,
                                    const float* __restrict__ kern,
                                    const float* __restrict__ a) {
    extern __shared__ char vsm[];
    int tid = threadIdx.x;
    int bx = blockIdx.x;

    if (bx >= 256) {
        int hb = bx - 256;
        if (tid < 32) g_count[hb * 32 + tid] = 0;
        if (hb == 0 && tid == 32) g_done = 0;
        int wid = tid >> 5, lane = tid & 31;
        int row = hb * 8 + wid;
        const float4* kr = reinterpret_cast<const float4*>(kern + (size_t)row * ROWLEN);
        const float4* a4 = reinterpret_cast<const float4*>(a);
        float s = 0.f, d = 0.f;
        for (int j = lane; j < ROWLEN / 4; j += 32) {
            float4 kv = kr[j], av = __ldg(&a4[j]);
            s += kv.x * kv.x + kv.y * kv.y + kv.z * kv.z + kv.w * kv.w;
            d += kv.x * av.x + kv.y * av.y + kv.z * av.z + kv.w * av.w;
        }
#pragma unroll
        for (int o = 16; o > 0; o >>= 1) {
            s += __shfl_xor_sync(0xffffffff, s, o);
            d += __shfl_xor_sync(0xffffffff, d, o);
        }
        if (lane == 0) { g_dotv[row] = d; g_nrm[row] = s; }
        return;
    }

    float* w_s = (float*)vsm;
    __half* tile = (__half*)(vsm + 6144);

    for (int i = tid; i < ROWLEN; i += 256) {
        int c = i / 9, k = i % 9;
        w_s[c * 12 + k] = a[i];
    }
    __syncthreads();

    int g = bx << 8;
    int b = g >> 12;
    int px0 = g & 4095;
    const float* ip = in + (size_t)b * Cin * HW + px0 + tid;

    float acc[9];
#pragma unroll
    for (int k = 0; k < 9; k++) acc[k] = 0.f;

#pragma unroll 4
    for (int c = 0; c < Cin; c++) {
        float v = ip[(size_t)c * HW];
        tile[c * VP_PITCH + tid] = __float2half_rn(v);
        float4 w0 = *reinterpret_cast<const float4*>(&w_s[c * 12]);
        float4 w1 = *reinterpret_cast<const float4*>(&w_s[c * 12 + 4]);
        float w8 = w_s[c * 12 + 8];
        acc[0] += v * w0.x; acc[1] += v * w0.y; acc[2] += v * w0.z; acc[3] += v * w0.w;
        acc[4] += v * w1.x; acc[5] += v * w1.y; acc[6] += v * w1.z; acc[7] += v * w1.w;
        acc[8] += v * w8;
    }
    float* tp = g_T + (size_t)b * 9 * HW + px0 + tid;
#pragma unroll
    for (int k = 0; k < 9; k++) tp[k * HW] = acc[k];
    __syncthreads();

    for (int i = tid; i < 256 * 64; i += 256) {
        int p = i >> 6, cq = i & 63;
        __half h0 = tile[(2 * cq) * VP_PITCH + p];
        __half h1 = tile[(2 * cq + 1) * VP_PITCH + p];
        reinterpret_cast<__half2*>(g_Bh)[(((size_t)(g + p)) << 6) + cq] =
            __halves2half2(h0, h1);
    }
}

// ---------------------------------------------------------------------------
// voteBCombine: 256 blocks x 256 px; last block runs combine.
// ---------------------------------------------------------------------------
__global__ void voteBCombine_kernel(const float* __restrict__ a,
                                    const float* __restrict__ bptr,
                                    float* __restrict__ out, long long out_size) {
    __shared__ int hist[TBL];
    __shared__ float ae[9];
    __shared__ int slast;
    int tid = threadIdx.x;
    for (int i = tid; i < TBL; i += 256) hist[i] = 0;
    if (tid < 9) ae[tid] = a[ROWLEN + tid];
    __syncthreads();

    int g = (blockIdx.x << 8) + tid;
    int b = g >> 12;
    int p = g & 4095;
    int y = p >> 6, x = p & 63;
    const float* tb = g_T + (size_t)b * 9 * HW;
    float s = 0.f;
#pragma unroll
    for (int dy = 0; dy < 3; dy++) {
        int gy = y + dy - 1;
        if (gy < 0 || gy >= Hh) continue;
#pragma unroll
        for (int dx = 0; dx < 3; dx++) {
            int gx = x + dx - 1;
            if (gx < 0 || gx >= Ww) continue;
            int k = dy * 3 + dx;
            s += tb[k * HW + gy * Ww + gx] + 0.5f * ae[k];
        }
    }
    int vi = (int)floorf((s + bptr[0]) / Rr);
    int vb = vi % TBL;
    if (vb < 0) vb = -vb;
    atomicAdd(&hist[vb], 1);
    __syncthreads();
    for (int i = tid; i < TBL; i += 256) {
        int c = hist[i];
        if (c) atomicAdd(&g_count[i], c);
    }

    __threadfence();
    __syncthreads();
    if (tid == 0) slast = (atomicAdd(&g_done, 1) == (int)gridDim.x - 1) ? 1 : 0;
    __syncthreads();
    if (!slast) return;

    __shared__ float sred[256];
    __shared__ int sbkt[Oc];
    __shared__ int sval[256];
    __shared__ int sidx[256];
    __shared__ int snact;
    if (tid == 0) snact = 0;
    sred[tid] = g_nrm[tid];
    __syncthreads();
    for (int st = 128; st > 0; st >>= 1) {
        if (tid < st) sred[tid] = fmaxf(sred[tid], sred[tid + st]);
        __syncthreads();
    }
    {
        float sn = g_nrm[tid];
        float scale = Uu / sqrtf(sred[0]);
        float dot = scale * g_dotv[tid];
        float pw = scale * scale * sn;
        float acc = 0.f, tt = pw;
#pragma unroll
        for (int i = 0; i < 9; i++) { acc += tt * ae[i]; tt = tt * tt; }
        int hi = (int)floorf((dot + acc + bptr[0]) / Rr);
        int bkt = hi % TBL;
        if (bkt < 0) bkt = -bkt;
        sbkt[tid] = bkt;
    }
    int bv = -1, bi = 0;
#pragma unroll
    for (int q = 0; q < 4; q++) {
        int idx = tid + q * 256;
        int v = *((volatile int*)&g_count[idx]);
        if (v > bv) { bv = v; bi = idx; }
    }
    sval[tid] = bv;
    sidx[tid] = bi;
    __syncthreads();
    for (int st = 128; st > 0; st >>= 1) {
        if (tid < st) {
            int v2 = sval[tid + st], i2 = sidx[tid + st];
            if (v2 > sval[tid] || (v2 == sval[tid] && i2 < sidx[tid])) {
                sval[tid] = v2;
                sidx[tid] = i2;
            }
        }
        __syncthreads();
    }
    int winner = sidx[0];
    {
        int m = (sbkt[tid] == winner) ? 1 : 0;
        g_maskA[tid] = m;
        if (m) { int pos = atomicAdd(&snact, 1); g_active[pos] = tid; }
        if (out_size >= CONV_ELEMS + 1 + Oc) out[CONV_ELEMS + 1 + tid] = m ? 1.f : 0.f;
    }
    if (tid == 0 && out_size >= CONV_ELEMS + 1) out[CONV_ELEMS] = (float)winner;
    __syncthreads();
    if (tid == 0) g_nactive = snact;
}

// ---------------------------------------------------------------------------
// prepA: gather compacted active weights -> g_Ah fp16. 1152 blocks.
// ---------------------------------------------------------------------------
__global__ void prepA_kernel(const float* __restrict__ kern) {
    int idx = blockIdx.x * 256 + threadIdx.x;
    int c = idx & 127;
    int m = (idx >> 7) & 255;
    int k = idx >> 15;
    int nact = g_nactive;
    float v = 0.f;
    if (m < nact) {
        int oc = g_active[m];
        v = kern[(size_t)oc * ROWLEN + c * 9 + k];
    }
    g_Ah[idx] = __float2half_rn(v);
}

// ---------------------------------------------------------------------------
// Main conv: 9 shifted GEMMs, single-term fp16, compacted oc list,
// ldmatrix fragment loads.
// grid (512, 5): by<4 conv tiles (M=128px x N=64oc, exit if n0>=nact);
// by==4 zeroes inactive output planes.
// 8 warps 4(M)x2(N); 9 full-K double-buffered steps.
// smem: patch 264px x 272B [0,71808), weights 2 x 64 x 272B [71808,106624),
//       act [106624,106880). Pitch 272 (mod 128 = 16) -> LDSM conflict-free.
// ---------------------------------------------------------------------------
#define PSTR 136                       // halfs per pixel row (272 B)
#define PROWB 272
#define SM_PH 0
#define SM_W 71808
#define WBUF 17408
#define WROWB 272
#define SM_ACT 106624
#define SM_TOT 106880

__global__ void __launch_bounds__(256, 2)
conv_mma_kernel(float* __restrict__ out) {
    extern __shared__ char smem[];
    const int tid = threadIdx.x;
    const int lane = tid & 31;
    const int wid = tid >> 5;
    const int nact = g_nactive;

    if (blockIdx.y == 4) {
        float4 z = make_float4(0.f, 0.f, 0.f, 0.f);
        for (int plane = blockIdx.x; plane < 4096; plane += 512) {
            if (g_maskA[plane & 255]) continue;
            float4* p = reinterpret_cast<float4*>(out + (size_t)plane * HW);
#pragma unroll
            for (int i = 0; i < 4; i++) p[tid + i * 256] = z;
        }
        return;
    }

    const int n0 = blockIdx.y << 6;
    if (n0 >= nact) return;

    const int pxg = blockIdx.x << 7;
    const int bb = pxg >> 12;
    const int y0 = (pxg & 4095) >> 6;

    uint32_t sb = smem_u32(smem);

    if (tid < 64) {
        int nn = n0 + tid;
        ((int*)(smem + SM_ACT))[tid] = (nn < nact) ? g_active[nn] : -1;
    }

    // patch: 264 px-rows x 16 chunks
    for (int i = tid; i < 264 * 16; i += 256) {
        int row = i >> 4, ch = i & 15;
        int pr = row / 66, pc = row - pr * 66;
        int gy = y0 - 1 + pr, gx = pc - 1;
        bool v = ((unsigned)gy < 64u) && ((unsigned)gx < 64u);
        const __half* src = v ? g_Bh + (((size_t)(bb << 12) + gy * 64 + gx) * 128 + ch * 8) : g_Bh;
        cp_async16(sb + SM_PH + row * PROWB + ch * 16, src, v);
    }
    // weights step 0 (k=0, full 128 c): 64 rows x 16 chunks
    for (int i = tid; i < 1024; i += 256) {
        int row = i >> 4, c16 = i & 15;
        const __half* src = g_Ah + ((size_t)(n0 + row) * 128 + c16 * 8);
        cp_async16(sb + SM_W + row * WROWB + c16 * 16, src, true);
    }
    CP_COMMIT();

    float d[2][4][4];
#pragma unroll
    for (int a = 0; a < 2; a++)
#pragma unroll
        for (int b2 = 0; b2 < 4; b2++)
#pragma unroll
            for (int c = 0; c < 4; c++) d[a][b2][c] = 0.f;

    const int pxbase = (wid & 3) << 5;   // 0,32,64,96
    const int nbase = (wid >> 2) << 5;   // 0,32
    const int gq = lane >> 3;            // ldmatrix tile group 0..3
    const int rq = lane & 7;             // row within tile

    // B ldmatrix lane address components (row = n, col = k-chunk)
    const int b_nrow = nbase + ((gq >> 1) << 3) + rq;   // + 0/8 (+16 for 2nd LDSM)
    const int b_col = (gq & 1) << 3;                    // 0/8 halfs

    // A lane pixel index (within 128-px tile) per mf: m-off = (gq&1)*8
    const int a_koff = (gq >> 1) << 3;                  // k-chunk 0/8

    for (int s = 0; s < 9; s++) {
        if (s < 8) {
            int k1 = s + 1;
            for (int i = tid; i < 1024; i += 256) {
                int row = i >> 4, c16 = i & 15;
                const __half* src = g_Ah + ((size_t)(k1 * 256 + n0 + row) * 128 + c16 * 8);
                cp_async16(sb + SM_W + (k1 & 1) * WBUF + row * WROWB + c16 * 16, src, true);
            }
            CP_COMMIT();
            CP_WAIT(1);
        } else {
            CP_WAIT(0);
        }
        __syncthreads();

        const int dy = s / 3, dx = s - dy * 3;
        const uint32_t wb = sb + SM_W + (s & 1) * WBUF;

        // per-k-step base addresses (loop-invariant over cs)
        uint32_t aaddr[2];
#pragma unroll
        for (int mf = 0; mf < 2; mf++) {
            int pix = pxbase + mf * 16 + ((gq & 1) << 3) + rq;
            int prow = ((pix >> 6) + dy) * 66 + (pix & 63) + dx;
            aaddr[mf] = sb + SM_PH + prow * PROWB + a_koff * 2;
        }
        uint32_t baddr0 = wb + b_nrow * WROWB + b_col * 2;
        uint32_t baddr1 = baddr0 + 16 * WROWB;

#pragma unroll
        for (int cs = 0; cs < 8; cs++) {
            const int co = cs * 32;   // 16 halfs = 32 bytes per step
            uint32_t ah[2][4];
#pragma unroll
            for (int mf = 0; mf < 2; mf++)
                LDSM_X4(ah[mf][0], ah[mf][1], ah[mf][2], ah[mf][3], aaddr[mf] + co);
            uint32_t b0, b1, b2, b3, b4, b5, b6, b7;
            LDSM_X4(b0, b1, b2, b3, baddr0 + co);
            LDSM_X4(b4, b5, b6, b7, baddr1 + co);
#pragma unroll
            for (int mf = 0; mf < 2; mf++) {
                MMA16816F(d[mf][0], ah[mf], b0, b1);
                MMA16816F(d[mf][1], ah[mf], b2, b3);
                MMA16816F(d[mf][2], ah[mf], b4, b5);
                MMA16816F(d[mf][3], ah[mf], b6, b7);
            }
        }
        __syncthreads();
    }

    // epilogue: compacted oc scatter
    const int* act = (const int*)(smem + SM_ACT);
    const int rr = lane >> 2;
#pragma unroll
    for (int mf = 0; mf < 2; mf++) {
#pragma unroll
        for (int nf = 0; nf < 4; nf++) {
            int col = nbase + nf * 8 + (lane & 3) * 2;
            int oc0 = act[col];
            int oc1 = act[col + 1];
#pragma unroll
            for (int h = 0; h < 2; h++) {
                int row = pxbase + mf * 16 + rr + h * 8;
                int y = y0 + (row >> 6);
                int x = row & 63;
                size_t pixoff = (size_t)y * 64 + x;
                if (oc0 >= 0) out[(((size_t)bb * Oc + oc0) << 12) + pixoff] = d[mf][nf][h * 2 + 0];
                if (oc1 >= 0) out[(((size_t)bb * Oc + oc1) << 12) + pixoff] = d[mf][nf][h * 2 + 1];
            }
        }
    }
}

// ---------------------------------------------------------------------------
extern "C" void kernel_launch(void* const* d_in, const int* in_sizes, int n_in,
                              void* d_out, int out_size) {
    const float* inp = (const float*)d_in[0];
    const float* kern = (const float*)d_in[1];
    const float* a = (const float*)d_in[2];
    const float* b = (const float*)d_in[3];
    float* out = (float*)d_out;

    cudaFuncSetAttribute(votePrepHash_kernel,
                         cudaFuncAttributeMaxDynamicSharedMemorySize, VP_SMEM);
    cudaFuncSetAttribute(conv_mma_kernel,
                         cudaFuncAttributeMaxDynamicSharedMemorySize, SM_TOT);

    votePrepHash_kernel<<<288, 256, VP_SMEM>>>(inp, kern, a);
    voteBCombine_kernel<<<256, 256>>>(a, b, out, (long long)out_size);
    prepA_kernel<<<1152, 256>>>(kern);
    conv_mma_kernel<<<dim3(512, 5), 256, SM_TOT>>>(out);
}